// round 7
// baseline (speedup 1.0000x reference)
#include <cuda_runtime.h>

#define N 4096
#define NN (1u << 24)  // 4096*4096

// Scratch (no device allocation allowed). 16B-aligned so float4 loads are legal.
__device__ __align__(16) float g_z0r[N];
__device__ __align__(16) float g_z0i[N];
__device__ __align__(16) float g_x0r[N];
__device__ __align__(16) float g_x0i[N];
__device__ __align__(16) float g_zir[N];  // Re(z_i) — only the real part is needed

// Kernel 0: gather column 0 of z and x (stride-N reads) into packed scratch.
__global__ void gather_vec_kernel(const float* __restrict__ xr,
                                  const float* __restrict__ xi,
                                  const float* __restrict__ zr,
                                  const float* __restrict__ zi) {
    int t = blockIdx.x * blockDim.x + threadIdx.x;
    if (t < N) {
        size_t idx = (size_t)t * N;
        g_z0r[t] = zr[idx];
        g_z0i[t] = zi[idx];
        g_x0r[t] = xr[idx];
        g_x0i[t] = xi[idx];
    }
}

// Kernel 1: Re(z_i) = 0.5*(Ar@z0r - Ai@z0i + Br@x0r - Bi@x0i). One CTA/row.
// Streams 4 matrix rows (64 KB) per CTA with float4 loads.
__global__ __launch_bounds__(256) void matvec_kernel(const float* __restrict__ Ar,
                                                     const float* __restrict__ Ai,
                                                     const float* __restrict__ Br,
                                                     const float* __restrict__ Bi) {
    const int m = blockIdx.x;
    const size_t base = (size_t)m * N;

    const float4* ar4 = (const float4*)(Ar + base);
    const float4* ai4 = (const float4*)(Ai + base);
    const float4* br4 = (const float4*)(Br + base);
    const float4* bi4 = (const float4*)(Bi + base);
    const float4* vzr4 = (const float4*)g_z0r;
    const float4* vzi4 = (const float4*)g_z0i;
    const float4* vxr4 = (const float4*)g_x0r;
    const float4* vxi4 = (const float4*)g_x0i;

    float sr = 0.f;
    for (int k = threadIdx.x; k < N / 4; k += 256) {
        float4 a_r = ar4[k];
        float4 a_i = ai4[k];
        float4 b_r = br4[k];
        float4 b_i = bi4[k];
        float4 zr = vzr4[k];
        float4 zi = vzi4[k];
        float4 xr = vxr4[k];
        float4 xi = vxi4[k];

        sr += a_r.x * zr.x - a_i.x * zi.x + b_r.x * xr.x - b_i.x * xi.x;
        sr += a_r.y * zr.y - a_i.y * zi.y + b_r.y * xr.y - b_i.y * xi.y;
        sr += a_r.z * zr.z - a_i.z * zi.z + b_r.z * xr.z - b_i.z * xi.z;
        sr += a_r.w * zr.w - a_i.w * zi.w + b_r.w * xr.w - b_i.w * xi.w;
    }

    for (int off = 16; off > 0; off >>= 1)
        sr += __shfl_down_sync(0xffffffffu, sr, off);

    __shared__ float red_r[8];
    int lane = threadIdx.x & 31;
    int wid = threadIdx.x >> 5;
    if (lane == 0) red_r[wid] = sr;
    __syncthreads();
    if (threadIdx.x == 0) {
        float tr = 0.f;
        #pragma unroll
        for (int w = 0; w < 8; w++) tr += red_r[w];
        g_zir[m] = 0.5f * tr;
    }
}

// Kernel 2: zj_re[r,c] = (c<4095) ? z_re[r,c+1] : Re(z_i)[r];
//           y_re = Re(z_i)[r] + zj_re.
// Output layout (derived from rounds 2-6 evidence):
//   out = [ y_t.real (NN floats) | z_j.real (NN floats) ]  == out_size exactly.
__global__ __launch_bounds__(256) void epilogue_kernel(const float* __restrict__ zr,
                                                       float* __restrict__ out) {
    unsigned idx = blockIdx.x * 256u + threadIdx.x;  // 0 .. NN-1
    int r = idx >> 12;
    int c = idx & (N - 1);
    float zvr = g_zir[r];  // broadcast within warp (same r)

    float jr = (c < N - 1) ? zr[idx + 1] : zvr;

    out[idx]           = zvr + jr;  // y_t.real
    out[1ull*NN + idx] = jr;        // z_j.real
}

extern "C" void kernel_launch(void* const* d_in, const int* in_sizes, int n_in,
                              void* d_out, int out_size) {
    const float* xr = (const float*)d_in[0];
    const float* xi = (const float*)d_in[1];
    const float* zr = (const float*)d_in[2];
    const float* zi = (const float*)d_in[3];
    const float* Ar = (const float*)d_in[4];
    const float* Ai = (const float*)d_in[5];
    const float* Br = (const float*)d_in[6];
    const float* Bi = (const float*)d_in[7];

    gather_vec_kernel<<<(N + 255) / 256, 256>>>(xr, xi, zr, zi);
    matvec_kernel<<<N, 256>>>(Ar, Ai, Br, Bi);
    epilogue_kernel<<<NN / 256, 256>>>(zr, (float*)d_out);
}

// round 8
// speedup vs baseline: 1.4791x; 1.4791x over previous
#include <cuda_runtime.h>

#define N 4096
#define NN (1u << 24)  // 4096*4096

// Scratch (no device allocation allowed). 16B-aligned so float4 loads are legal.
__device__ __align__(16) float g_z0r[N];
__device__ __align__(16) float g_z0i[N];
__device__ __align__(16) float g_x0r[N];
__device__ __align__(16) float g_x0i[N];

// Kernel 0: gather column 0 of z and x (stride-N reads) into packed scratch.
__global__ void gather_vec_kernel(const float* __restrict__ xr,
                                  const float* __restrict__ xi,
                                  const float* __restrict__ zr,
                                  const float* __restrict__ zi) {
    int t = blockIdx.x * blockDim.x + threadIdx.x;
    if (t < N) {
        size_t idx = (size_t)t * N;
        g_z0r[t] = zr[idx];
        g_z0i[t] = zi[idx];
        g_x0r[t] = xr[idx];
        g_x0i[t] = xi[idx];
    }
}

// Fused kernel: one CTA per row m.
// Phase 1: Re(z_i)[m] = 0.5*(Ar[m,:]@z0r - Ai[m,:]@z0i + Br[m,:]@x0r - Bi[m,:]@x0i)
//   Matrix rows streamed with __ldcs (evict-first) so the 64KB vector working
//   set stays L1-resident across all CTAs on an SM.
// Phase 2: row-m epilogue, float4-vectorized:
//   zj[m,c] = (c<4095) ? z_re[m,c+1] : Re(z_i)[m];  y[m,c] = Re(z_i)[m] + zj[m,c]
// Output layout: out = [ y_t.real (NN) | z_j.real (NN) ].
__global__ __launch_bounds__(256) void fused_kernel(const float* __restrict__ Ar,
                                                    const float* __restrict__ Ai,
                                                    const float* __restrict__ Br,
                                                    const float* __restrict__ Bi,
                                                    const float* __restrict__ zr,
                                                    float* __restrict__ out) {
    const int m = blockIdx.x;
    const size_t base = (size_t)m * N;

    const float4* ar4 = (const float4*)(Ar + base);
    const float4* ai4 = (const float4*)(Ai + base);
    const float4* br4 = (const float4*)(Br + base);
    const float4* bi4 = (const float4*)(Bi + base);
    const float4* vzr4 = (const float4*)g_z0r;
    const float4* vzi4 = (const float4*)g_z0i;
    const float4* vxr4 = (const float4*)g_x0r;
    const float4* vxi4 = (const float4*)g_x0i;

    float sr = 0.f;
    #pragma unroll 4
    for (int k = threadIdx.x; k < N / 4; k += 256) {
        float4 a_r = __ldcs(ar4 + k);   // streaming: evict-first
        float4 a_i = __ldcs(ai4 + k);
        float4 b_r = __ldcs(br4 + k);
        float4 b_i = __ldcs(bi4 + k);
        float4 vz_r = vzr4[k];          // L1-resident working set
        float4 vz_i = vzi4[k];
        float4 vx_r = vxr4[k];
        float4 vx_i = vxi4[k];

        sr += a_r.x * vz_r.x - a_i.x * vz_i.x + b_r.x * vx_r.x - b_i.x * vx_i.x;
        sr += a_r.y * vz_r.y - a_i.y * vz_i.y + b_r.y * vx_r.y - b_i.y * vx_i.y;
        sr += a_r.z * vz_r.z - a_i.z * vz_i.z + b_r.z * vx_r.z - b_i.z * vx_i.z;
        sr += a_r.w * vz_r.w - a_i.w * vz_i.w + b_r.w * vx_r.w - b_i.w * vx_i.w;
    }

    for (int off = 16; off > 0; off >>= 1)
        sr += __shfl_down_sync(0xffffffffu, sr, off);

    __shared__ float red[8];
    __shared__ float s_zir;
    int lane = threadIdx.x & 31;
    int wid = threadIdx.x >> 5;
    if (lane == 0) red[wid] = sr;
    __syncthreads();
    if (threadIdx.x == 0) {
        float tr = 0.f;
        #pragma unroll
        for (int w = 0; w < 8; w++) tr += red[w];
        s_zir = 0.5f * tr;
    }
    __syncthreads();
    const float zvr = s_zir;

    // Phase 2: float4 epilogue over this row's 4096 columns (1024 float4).
    const float4* zrow4 = (const float4*)(zr + base);
    const float* zrow = zr + base;
    float4* outy4 = (float4*)out + (size_t)m * (N / 4);
    float4* outj4 = (float4*)out + (size_t)(NN / 4) + (size_t)m * (N / 4);

    #pragma unroll 4
    for (int t = threadIdx.x; t < N / 4; t += 256) {
        float4 v = zrow4[t];                       // cols 4t .. 4t+3
        int c_next = 4 * t + 4;
        float nxt = (c_next < N) ? zrow[c_next] : zvr;  // L1 hit (neighbor's lead elem)

        float4 j = make_float4(v.y, v.z, v.w, nxt);
        float4 y = make_float4(zvr + j.x, zvr + j.y, zvr + j.z, zvr + j.w);

        outy4[t] = y;
        outj4[t] = j;
    }
}

extern "C" void kernel_launch(void* const* d_in, const int* in_sizes, int n_in,
                              void* d_out, int out_size) {
    const float* xr = (const float*)d_in[0];
    const float* xi = (const float*)d_in[1];
    const float* zr = (const float*)d_in[2];
    const float* zi = (const float*)d_in[3];
    const float* Ar = (const float*)d_in[4];
    const float* Ai = (const float*)d_in[5];
    const float* Br = (const float*)d_in[6];
    const float* Bi = (const float*)d_in[7];

    gather_vec_kernel<<<(N + 255) / 256, 256>>>(xr, xi, zr, zi);
    fused_kernel<<<N, 256>>>(Ar, Ai, Br, Bi, zr, (float*)d_out);
}